// round 16
// baseline (speedup 1.0000x reference)
#include <cuda_runtime.h>
#include <math_constants.h>
#include <cstdint>

#define NOUT   257
#define NBATCH 32768
#define RPB    8          // warps per block; each warp does 2 rows

// ---- f32x2 packed helpers (sm_103a native) ----
__device__ __forceinline__ uint64_t pk2(float lo, float hi) {
    uint64_t r;
    asm("mov.b64 %0, {%1, %2};" : "=l"(r) : "f"(lo), "f"(hi));
    return r;
}
__device__ __forceinline__ void upk2(uint64_t v, float& lo, float& hi) {
    asm("mov.b64 {%0, %1}, %2;" : "=f"(lo), "=f"(hi) : "l"(v));
}
__device__ __forceinline__ uint64_t fma2(uint64_t a, uint64_t b, uint64_t c) {
    uint64_t d;
    asm("fma.rn.f32x2 %0, %1, %2, %3;" : "=l"(d) : "l"(a), "l"(b), "l"(c));
    return d;
}
__device__ __forceinline__ uint64_t mul2(uint64_t a, uint64_t b) {
    uint64_t d;
    asm("mul.rn.f32x2 %0, %1, %2;" : "=l"(d) : "l"(a), "l"(b));
    return d;
}
__device__ __forceinline__ uint64_t add2(uint64_t a, uint64_t b) {
    uint64_t d;
    asm("add.rn.f32x2 %0, %1, %2;" : "=l"(d) : "l"(a), "l"(b));
    return d;
}

#define ONE2   0x3F8000003F800000ull   // ( 1.0f,  1.0f)
#define NEG2   0xBF800000BF800000ull   // (-1.0f, -1.0f)
#define C2P    0x3F3504F33F3504F3ull   // ( c,  c), c = sqrt(2)/2
#define C2N    0xBF3504F3BF3504F3ull   // (-c, -c)
#define HALF2  0x3F0000003F000000ull   // ( 0.5, 0.5)

__device__ __forceinline__ uint64_t sub2(uint64_t a, uint64_t b) {
    return fma2(NEG2, b, a);           // a - b
}
__device__ __forceinline__ uint64_t neg2(uint64_t a) {
    return mul2(NEG2, a);
}

// Packed cross-lane DIF stage over all 8 slots, butterfly distance H.
// Each uint64 carries (row0, row1) of one complex component.
template<int H>
__device__ __forceinline__ void dif_stage_p(uint64_t* Zr, uint64_t* Zi,
                                            uint64_t s2, uint64_t wc2,
                                            uint64_t nws2, uint64_t ws2)
{
    #pragma unroll
    for (int r = 0; r < 8; ++r) {
        const uint64_t orr = __shfl_xor_sync(0xffffffffu, Zr[r], H);
        const uint64_t oii = __shfl_xor_sync(0xffffffffu, Zi[r], H);
        const uint64_t dr = fma2(s2, Zr[r], orr);
        const uint64_t di = fma2(s2, Zi[r], oii);
        Zr[r] = fma2(wc2, dr, mul2(nws2, di));
        Zi[r] = fma2(wc2, di, mul2(ws2,  dr));
    }
}

// Apply per-lane complex twiddle (wr,wi) to packed slot s (both rows).
#define APPLY_TW(s, wr, wi) do {                                         \
    const uint64_t _wr2  = pk2((wr), (wr));                              \
    const uint64_t _wi2  = pk2((wi), (wi));                              \
    const uint64_t _nwi2 = pk2(-(wi), -(wi));                            \
    const uint64_t _tr = fma2(Zr[s], _wr2, mul2(_nwi2, Zi[s]));          \
    Zi[s] = fma2(Zr[s], _wi2, mul2(Zi[s], _wr2));                        \
    Zr[s] = _tr;                                                         \
} while (0)

__global__ __launch_bounds__(256, 4)
void rfft512_warp2(const float* __restrict__ x,
                   float* __restrict__ yre,
                   float* __restrict__ yim)
{
    // Both rows' Z staged as float4 (r0.re, r0.im, r1.re, r1.im) at
    // float4 addr a = k + (k>>5): conflict-free STS.128 scatter and
    // LDS.128 gather (proved via per-phase br3 analysis).
    __shared__ float4 ssz[RPB][264];

    const int lane = threadIdx.x & 31;
    const int w    = threadIdx.x >> 5;
    const int row0 = (blockIdx.x * RPB + w) * 2;
    const float* xr0 = x + row0 * 512;
    const float* xr1 = xr0 + 512;
    float4* sz = ssz[w];

    // ---- load both rows: z[m] = x[2m] + i x[2m+1] (raw), m = lane + 32r ----
    uint64_t Zr[8], Zi[8];
    #pragma unroll
    for (int r = 0; r < 8; ++r) {
        const float2 a = *reinterpret_cast<const float2*>(xr0 + 2 * (lane + 32 * r));
        const float2 b = *reinterpret_cast<const float2*>(xr1 + 2 * (lane + 32 * r));
        Zr[r] = pk2(a.x, b.x);
        Zi[r] = pk2(a.y, b.y);
    }

    // ---- step A: radix-8 DIF over reg index -> slot r holds k2 = br3(r) ----
    {   // h=4, twiddles W8^{0..3}
        uint64_t dr, di, s;
        s = add2(Zr[0], Zr[4]); dr = sub2(Zr[0], Zr[4]); Zr[0] = s; Zr[4] = dr;
        s = add2(Zi[0], Zi[4]); di = sub2(Zi[0], Zi[4]); Zi[0] = s; Zi[4] = di;

        dr = sub2(Zr[1], Zr[5]); di = sub2(Zi[1], Zi[5]);
        Zr[1] = add2(Zr[1], Zr[5]); Zi[1] = add2(Zi[1], Zi[5]);
        Zr[5] = mul2(C2P, add2(dr, di)); Zi[5] = mul2(C2P, sub2(di, dr));

        dr = sub2(Zr[2], Zr[6]); di = sub2(Zi[2], Zi[6]);
        Zr[2] = add2(Zr[2], Zr[6]); Zi[2] = add2(Zi[2], Zi[6]);
        Zr[6] = di; Zi[6] = neg2(dr);

        dr = sub2(Zr[3], Zr[7]); di = sub2(Zi[3], Zi[7]);
        Zr[3] = add2(Zr[3], Zr[7]); Zi[3] = add2(Zi[3], Zi[7]);
        Zr[7] = mul2(C2P, sub2(di, dr)); Zi[7] = mul2(C2N, add2(dr, di));
    }
    {   // h=2, twiddles 1, -i
        uint64_t dr, di, s;
        s = add2(Zr[0], Zr[2]); dr = sub2(Zr[0], Zr[2]); Zr[0] = s; Zr[2] = dr;
        s = add2(Zi[0], Zi[2]); di = sub2(Zi[0], Zi[2]); Zi[0] = s; Zi[2] = di;

        dr = sub2(Zr[1], Zr[3]); di = sub2(Zi[1], Zi[3]);
        Zr[1] = add2(Zr[1], Zr[3]); Zi[1] = add2(Zi[1], Zi[3]);
        Zr[3] = di; Zi[3] = neg2(dr);

        s = add2(Zr[4], Zr[6]); dr = sub2(Zr[4], Zr[6]); Zr[4] = s; Zr[6] = dr;
        s = add2(Zi[4], Zi[6]); di = sub2(Zi[4], Zi[6]); Zi[4] = s; Zi[6] = di;

        dr = sub2(Zr[5], Zr[7]); di = sub2(Zi[5], Zi[7]);
        Zr[5] = add2(Zr[5], Zr[7]); Zi[5] = add2(Zi[5], Zi[7]);
        Zr[7] = di; Zi[7] = neg2(dr);
    }
    {   // h=1
        uint64_t dr, di, s;
        #pragma unroll
        for (int p = 0; p < 8; p += 2) {
            s = add2(Zr[p], Zr[p + 1]); dr = sub2(Zr[p], Zr[p + 1]);
            Zr[p] = s; Zr[p + 1] = dr;
            s = add2(Zi[p], Zi[p + 1]); di = sub2(Zi[p], Zi[p + 1]);
            Zi[p] = s; Zi[p + 1] = di;
        }
    }

    // ---- step B: multiply slot (k2 = br3(slot)) by W_256^{lane*k2} ----
    {
        float w1r, w1i;
        __sincosf(-2.0f * CUDART_PI_F * (float)lane / 256.0f, &w1i, &w1r);
        const float w2r = w1r * w1r - w1i * w1i, w2i = 2.0f * w1r * w1i;
        const float w3r = w2r * w1r - w2i * w1i, w3i = w2r * w1i + w2i * w1r;
        const float w4r = w2r * w2r - w2i * w2i, w4i = 2.0f * w2r * w2i;
        const float w5r = w4r * w1r - w4i * w1i, w5i = w4r * w1i + w4i * w1r;
        const float w6r = w3r * w3r - w3i * w3i, w6i = 2.0f * w3r * w3i;
        const float w7r = w4r * w3r - w4i * w3i, w7i = w4r * w3i + w4i * w3r;

        APPLY_TW(4, w1r, w1i);   // k2=1
        APPLY_TW(2, w2r, w2i);   // k2=2
        APPLY_TW(6, w3r, w3i);   // k2=3
        APPLY_TW(1, w4r, w4i);   // k2=4
        APPLY_TW(5, w5r, w5i);   // k2=5
        APPLY_TW(3, w6r, w6i);   // k2=6
        APPLY_TW(7, w7r, w7i);   // k2=7
    }

    // ---- step C: 32-pt DIF across lanes (both rows ride each shuffle) ----
    {
        float uc, us;   // u = W_32^{lane&15}
        __sincosf(-CUDART_PI_F * (float)(lane & 15) / 16.0f, &us, &uc);
        const float p2c = uc * uc - us * us,     p2s = 2.0f * uc * us;
        const float p4c = p2c * p2c - p2s * p2s, p4s = 2.0f * p2c * p2s;
        const float p8c = p4c * p4c - p4s * p4s, p8s = 2.0f * p4c * p4s;

        {   // H=16: w = u
            const bool hi = (lane & 16) != 0;
            const float wc = hi ?  uc : 1.0f;
            const float ws = hi ?  us : 0.0f;
            dif_stage_p<16>(Zr, Zi, hi ? NEG2 : ONE2,
                            pk2(wc, wc), pk2(-ws, -ws), pk2(ws, ws));
        }
        {   // H=8: w = -u^2
            const bool hi = (lane & 8) != 0;
            const float wc = hi ? -p2c : 1.0f;
            const float ws = hi ? -p2s : 0.0f;
            dif_stage_p<8>(Zr, Zi, hi ? NEG2 : ONE2,
                           pk2(wc, wc), pk2(-ws, -ws), pk2(ws, ws));
        }
        {   // H=4: w = -u^4
            const bool hi = (lane & 4) != 0;
            const float wc = hi ? -p4c : 1.0f;
            const float ws = hi ? -p4s : 0.0f;
            dif_stage_p<4>(Zr, Zi, hi ? NEG2 : ONE2,
                           pk2(wc, wc), pk2(-ws, -ws), pk2(ws, ws));
        }
        {   // H=2: w = -u^8
            const bool hi = (lane & 2) != 0;
            const float wc = hi ? -p8c : 1.0f;
            const float ws = hi ? -p8s : 0.0f;
            dif_stage_p<2>(Zr, Zi, hi ? NEG2 : ONE2,
                           pk2(wc, wc), pk2(-ws, -ws), pk2(ws, ws));
        }
        {   // H=1: w = 1 (twiddle-free)
            const uint64_t s2 = (lane & 1) ? NEG2 : ONE2;
            #pragma unroll
            for (int r = 0; r < 8; ++r) {
                const uint64_t orr = __shfl_xor_sync(0xffffffffu, Zr[r], 1);
                const uint64_t oii = __shfl_xor_sync(0xffffffffu, Zi[r], 1);
                Zr[r] = fma2(s2, Zr[r], orr);
                Zi[r] = fma2(s2, Zi[r], oii);
            }
        }
    }
    // lane l, slot r holds Z[k2 + 8*kappa] for BOTH rows; k2=br3(r), kappa=br5(l)

    // ---- scatter both rows to smem as float4 at a = k + (k>>5) ----
    {
        const int kap  = __brev((unsigned)lane) >> 27;  // bitrev5(lane)
        const int base = 8 * kap + (kap >> 2);          // k + (k>>5), k=8kap+k2
        const int K2M[8] = {0, 4, 2, 6, 1, 5, 3, 7};
        #pragma unroll
        for (int r = 0; r < 8; ++r) {
            float a0, a1, b0, b1;
            upk2(Zr[r], a0, a1);
            upk2(Zi[r], b0, b1);
            sz[base + K2M[r]] = make_float4(a0, b0, a1, b1);
        }
    }
    __syncwarp();

    // ---- pair untangle (both rows packed): k = 32j + lane, j = 0..3 ----
    float* or0 = yre + row0 * NOUT;
    float* oi0 = yim + row0 * NOUT;
    float* or1 = or0 + NOUT;
    float* oi1 = oi0 + NOUT;
    {
        float bc, bs;   // W_512^lane
        __sincosf(-2.0f * CUDART_PI_F * (float)lane / 512.0f, &bs, &bc);

        // 0.5 * W_16^j, j = 0..3 (0.5 real-split factor folded in)
        const float CJ2[4] = { 0.5f,  0.46193976625564337f,
                               0.35355339059327379f,  0.19134171618254492f};
        const float SJ2[4] = { 0.0f, -0.19134171618254489f,
                              -0.35355339059327373f, -0.46193976625564337f};

        #pragma unroll
        for (int j = 0; j < 4; ++j) {
            const int k  = 32 * j + lane;
            const int km = (256 - k) & 255;           // partner (k=0 -> 0)

            const float4 Qk = sz[33 * j + lane];      // a = k + (k>>5)
            const float4 Qm = sz[km + (km >> 5)];

            const uint64_t Zkr = pk2(Qk.x, Qk.z), Zki = pk2(Qk.y, Qk.w);
            const uint64_t Zmr = pk2(Qm.x, Qm.z), Zmi = pk2(Qm.y, Qm.w);

            const uint64_t sxr = add2(Zkr, Zmr);      // 2*Fe.re
            const uint64_t dyi = sub2(Zki, Zmi);      // 2*Fe.im
            const uint64_t For = add2(Zki, Zmi);      // 2*Fo.re
            const uint64_t Foi = sub2(Zmr, Zkr);      // 2*Fo.im

            // w' = 0.5 * W_512^k = (bc + i bs) * (CJ2 + i SJ2)
            const float wc = fmaf(bc, CJ2[j], -bs * SJ2[j]);
            const float ws = fmaf(bc, SJ2[j],  bs * CJ2[j]);
            const uint64_t wc2  = pk2(wc, wc);
            const uint64_t ws2  = pk2(ws, ws);
            const uint64_t nws2 = pk2(-ws, -ws);

            const uint64_t P = fma2(wc2, For, mul2(nws2, Foi));
            const uint64_t Q = fma2(wc2, Foi, mul2(ws2,  For));
            const uint64_t A = mul2(HALF2, sxr);
            const uint64_t B = mul2(HALF2, dyi);

            float e0, e1;
            upk2(add2(A, P), e0, e1); or0[k] = e0;       or1[k] = e1;
            upk2(add2(B, Q), e0, e1); oi0[k] = e0;       oi1[k] = e1;
            upk2(sub2(A, P), e0, e1); or0[256 - k] = e0; or1[256 - k] = e1;
            upk2(sub2(Q, B), e0, e1); oi0[256 - k] = e0; oi1[256 - k] = e1;
        }
        if (lane == 0) {   // self-paired bin 128: X = Zr - i*Zi (both rows)
            const float4 Qc = sz[128 + (128 >> 5)];   // a = 132
            or0[128] =  Qc.x; oi0[128] = -Qc.y;
            or1[128] =  Qc.z; oi1[128] = -Qc.w;
        }
    }
}

extern "C" void kernel_launch(void* const* d_in, const int* in_sizes, int n_in,
                              void* d_out, int out_size)
{
    const float* x = (const float*)d_in[0];
    float* out = (float*)d_out;
    float* yre = out;                                  // [32768, 257]
    float* yim = out + (long long)NBATCH * NOUT;       // [32768, 257]

    rfft512_warp2<<<NBATCH / (RPB * 2), 32 * RPB>>>(x, yre, yim);
}

// round 17
// speedup vs baseline: 1.0863x; 1.0863x over previous
#include <cuda_runtime.h>
#include <math_constants.h>
#include <cstdint>

#define NOUT   257
#define NBATCH 32768
#define RPB    2          // warps (rows) per block: 64-thread blocks ->
                          // 21 co-resident blocks/SM at 48 regs (42 warps)

__device__ __forceinline__ void cmul(float ar, float ai, float br, float bi,
                                     float& cr, float& ci)
{
    cr = ar * br - ai * bi;
    ci = ar * bi + ai * br;
}

// ---- f32x2 packed helpers (sm_103a native) ----
__device__ __forceinline__ uint64_t pk2(float lo, float hi) {
    uint64_t r;
    asm("mov.b64 %0, {%1, %2};" : "=l"(r) : "f"(lo), "f"(hi));
    return r;
}
__device__ __forceinline__ void upk2(uint64_t v, float& lo, float& hi) {
    asm("mov.b64 {%0, %1}, %2;" : "=f"(lo), "=f"(hi) : "l"(v));
}
__device__ __forceinline__ uint64_t fma2(uint64_t a, uint64_t b, uint64_t c) {
    uint64_t d;
    asm("fma.rn.f32x2 %0, %1, %2, %3;" : "=l"(d) : "l"(a), "l"(b), "l"(c));
    return d;
}
__device__ __forceinline__ uint64_t mul2(uint64_t a, uint64_t b) {
    uint64_t d;
    asm("mul.rn.f32x2 %0, %1, %2;" : "=l"(d) : "l"(a), "l"(b));
    return d;
}

#define ONE2  0x3F8000003F800000ull   // ( 1.0f,  1.0f)
#define NEG2  0xBF800000BF800000ull   // (-1.0f, -1.0f)

// Packed cross-lane DIF stage, butterfly distance H (select-free).
template<int H>
__device__ __forceinline__ void dif_stage_p(uint64_t* Zr, uint64_t* Zi,
                                            uint64_t s2, uint64_t wc2,
                                            uint64_t nws2, uint64_t ws2)
{
    #pragma unroll
    for (int q = 0; q < 4; ++q) {
        const uint64_t orr = __shfl_xor_sync(0xffffffffu, Zr[q], H);
        const uint64_t oii = __shfl_xor_sync(0xffffffffu, Zi[q], H);
        const uint64_t dr = fma2(s2, Zr[q], orr);
        const uint64_t di = fma2(s2, Zi[q], oii);
        Zr[q] = fma2(wc2, dr, mul2(nws2, di));
        Zi[q] = fma2(wc2, di, mul2(ws2,  dr));
    }
}

__global__ __launch_bounds__(32 * RPB)
void rfft512_warp(const float* __restrict__ x,
                  float* __restrict__ yre,
                  float* __restrict__ yim)
{
    // Z staged interleaved (re,im) at float2 addr a = k + (k>>4)
    // (conflict-free scatter AND gather). Z is UNSCALED; the 1/2 from the
    // real-split untangle is folded into the untangle constants below.
    __shared__ float2 ssz[RPB][272];

    const int lane = threadIdx.x & 31;
    const int w    = threadIdx.x >> 5;
    const int row  = blockIdx.x * RPB + w;          // < 32768: 32-bit math safe
    const float* xr = x + row * 512;
    float2* sz = ssz[w];

    // ---- load z[m] = x[2m] + i x[2m+1], m = lane + 32 r (raw, no scale) ----
    float zr[8], zi[8];
    #pragma unroll
    for (int r = 0; r < 8; ++r) {
        float2 v = *reinterpret_cast<const float2*>(xr + 2 * (lane + 32 * r));
        zr[r] = v.x; zi[r] = v.y;
    }

    // ---- step A: radix-8 DIF over reg index -> slot r holds k2 = br3(r) ----
    const float C = 0.70710678118654752440f;
    {   // h=4, twiddles W8^{0..3}
        float dr, di;
        dr = zr[0] - zr[4]; di = zi[0] - zi[4];
        zr[0] += zr[4]; zi[0] += zi[4];
        zr[4] = dr; zi[4] = di;

        dr = zr[1] - zr[5]; di = zi[1] - zi[5];
        zr[1] += zr[5]; zi[1] += zi[5];
        zr[5] = C * (dr + di); zi[5] = C * (di - dr);

        dr = zr[2] - zr[6]; di = zi[2] - zi[6];
        zr[2] += zr[6]; zi[2] += zi[6];
        zr[6] = di; zi[6] = -dr;

        dr = zr[3] - zr[7]; di = zi[3] - zi[7];
        zr[3] += zr[7]; zi[3] += zi[7];
        zr[7] = C * (di - dr); zi[7] = -C * (dr + di);
    }
    {   // h=2, twiddles 1, -i
        float dr, di;
        dr = zr[0] - zr[2]; di = zi[0] - zi[2];
        zr[0] += zr[2]; zi[0] += zi[2]; zr[2] = dr; zi[2] = di;

        dr = zr[1] - zr[3]; di = zi[1] - zi[3];
        zr[1] += zr[3]; zi[1] += zi[3]; zr[3] = di; zi[3] = -dr;

        dr = zr[4] - zr[6]; di = zi[4] - zi[6];
        zr[4] += zr[6]; zi[4] += zi[6]; zr[6] = dr; zi[6] = di;

        dr = zr[5] - zr[7]; di = zi[5] - zi[7];
        zr[5] += zr[7]; zi[5] += zi[7]; zr[7] = di; zi[7] = -dr;
    }
    {   // h=1
        float dr, di;
        dr = zr[0] - zr[1]; di = zi[0] - zi[1];
        zr[0] += zr[1]; zi[0] += zi[1]; zr[1] = dr; zi[1] = di;
        dr = zr[2] - zr[3]; di = zi[2] - zi[3];
        zr[2] += zr[3]; zi[2] += zi[3]; zr[3] = dr; zi[3] = di;
        dr = zr[4] - zr[5]; di = zi[4] - zi[5];
        zr[4] += zr[5]; zi[4] += zi[5]; zr[5] = dr; zi[5] = di;
        dr = zr[6] - zr[7]; di = zi[6] - zi[7];
        zr[6] += zr[7]; zi[6] += zi[7]; zr[7] = dr; zi[7] = di;
    }

    // ---- step B: multiply slot (k2) by W_256^{lane * k2} (parallel form) ----
    {
        float w1r, w1i;
        __sincosf(-2.0f * CUDART_PI_F * (float)lane / 256.0f, &w1i, &w1r);
        float w2r, w2i, w3r, w3i, w4r, w4i, w5r, w5i, w6r, w6i, w7r, w7i;
        cmul(w1r, w1i, w1r, w1i, w2r, w2i);
        cmul(w2r, w2i, w1r, w1i, w3r, w3i);
        cmul(w2r, w2i, w2r, w2i, w4r, w4i);
        cmul(w4r, w4i, w1r, w1i, w5r, w5i);
        cmul(w3r, w3i, w3r, w3i, w6r, w6i);
        cmul(w4r, w4i, w3r, w3i, w7r, w7i);

        float tr, ti;
        cmul(zr[1], zi[1], w4r, w4i, tr, ti); zr[1] = tr; zi[1] = ti;  // k2=4
        cmul(zr[2], zi[2], w2r, w2i, tr, ti); zr[2] = tr; zi[2] = ti;  // k2=2
        cmul(zr[3], zi[3], w6r, w6i, tr, ti); zr[3] = tr; zi[3] = ti;  // k2=6
        cmul(zr[4], zi[4], w1r, w1i, tr, ti); zr[4] = tr; zi[4] = ti;  // k2=1
        cmul(zr[5], zi[5], w5r, w5i, tr, ti); zr[5] = tr; zi[5] = ti;  // k2=5
        cmul(zr[6], zi[6], w3r, w3i, tr, ti); zr[6] = tr; zi[6] = ti;  // k2=3
        cmul(zr[7], zi[7], w7r, w7i, tr, ti); zr[7] = tr; zi[7] = ti;  // k2=7
    }

    // ---- step C: 32-pt DIF across lanes, f32x2-packed over reg pairs ----
    {
        float uc, us;   // u = W_32^{lane&15}
        __sincosf(-CUDART_PI_F * (float)(lane & 15) / 16.0f, &us, &uc);
        const float p2c = uc * uc - us * us,     p2s = 2.0f * uc * us;
        const float p4c = p2c * p2c - p2s * p2s, p4s = 2.0f * p2c * p2s;
        const float p8c = p4c * p4c - p4s * p4s, p8s = 2.0f * p4c * p4s;

        uint64_t Zr[4], Zi[4];
        #pragma unroll
        for (int q = 0; q < 4; ++q) {
            Zr[q] = pk2(zr[2 * q], zr[2 * q + 1]);
            Zi[q] = pk2(zi[2 * q], zi[2 * q + 1]);
        }

        {   // H=16: w = u
            const bool hi = (lane & 16) != 0;
            const float wc = hi ?  uc : 1.0f;
            const float ws = hi ?  us : 0.0f;
            dif_stage_p<16>(Zr, Zi, hi ? NEG2 : ONE2,
                            pk2(wc, wc), pk2(-ws, -ws), pk2(ws, ws));
        }
        {   // H=8: w = -u^2
            const bool hi = (lane & 8) != 0;
            const float wc = hi ? -p2c : 1.0f;
            const float ws = hi ? -p2s : 0.0f;
            dif_stage_p<8>(Zr, Zi, hi ? NEG2 : ONE2,
                           pk2(wc, wc), pk2(-ws, -ws), pk2(ws, ws));
        }
        {   // H=4: w = -u^4
            const bool hi = (lane & 4) != 0;
            const float wc = hi ? -p4c : 1.0f;
            const float ws = hi ? -p4s : 0.0f;
            dif_stage_p<4>(Zr, Zi, hi ? NEG2 : ONE2,
                           pk2(wc, wc), pk2(-ws, -ws), pk2(ws, ws));
        }
        {   // H=2: w = -u^8
            const bool hi = (lane & 2) != 0;
            const float wc = hi ? -p8c : 1.0f;
            const float ws = hi ? -p8s : 0.0f;
            dif_stage_p<2>(Zr, Zi, hi ? NEG2 : ONE2,
                           pk2(wc, wc), pk2(-ws, -ws), pk2(ws, ws));
        }
        {   // H=1: w = 1 (twiddle-free)
            const uint64_t s2 = (lane & 1) ? NEG2 : ONE2;
            #pragma unroll
            for (int q = 0; q < 4; ++q) {
                const uint64_t orr = __shfl_xor_sync(0xffffffffu, Zr[q], 1);
                const uint64_t oii = __shfl_xor_sync(0xffffffffu, Zi[q], 1);
                Zr[q] = fma2(s2, Zr[q], orr);
                Zi[q] = fma2(s2, Zi[q], oii);
            }
        }

        #pragma unroll
        for (int q = 0; q < 4; ++q) {
            upk2(Zr[q], zr[2 * q], zr[2 * q + 1]);
            upk2(Zi[q], zi[2 * q], zi[2 * q + 1]);
        }
    }
    // lane l, slot r holds Z[k2 + 8*kappa], k2 = br3(r), kappa = br5(l)

    // ---- stage Z to smem (interleaved) at a = k + (k>>4): conflict-free ----
    {
        const int kap = __brev((unsigned)lane) >> 27;   // bitrev5(lane)
        const int base = 8 * kap + (kap >> 1);          // = 8kap + ((8kap+k2)>>4)
        const int K2M[8] = {0, 4, 2, 6, 1, 5, 3, 7};
        #pragma unroll
        for (int r = 0; r < 8; ++r)
            sz[base + K2M[r]] = make_float2(zr[r], zi[r]);
    }
    __syncwarp();

    // ---- pair untangle: k = 32j + lane (j=0..3) gives X[k] AND X[256-k] ----
    // 0.5 real-split factor folded into constants (CJ2 = CJ/2, SJ2 = SJ/2)
    // and into the output FMAs.
    float* orow = yre + row * NOUT;
    float* irow = yim + row * NOUT;
    {
        float bc, bs;   // W_512^lane
        __sincosf(-2.0f * CUDART_PI_F * (float)lane / 512.0f, &bs, &bc);

        // 0.5 * W_16^j, j = 0..3
        const float CJ2[4] = { 0.5f,  0.46193976625564337f,
                               0.35355339059327379f,  0.19134171618254492f};
        const float SJ2[4] = { 0.0f, -0.19134171618254489f,
                              -0.35355339059327373f, -0.46193976625564337f};

        #pragma unroll
        for (int j = 0; j < 4; ++j) {
            const int k  = 32 * j + lane;
            const int km = (256 - k) & 255;           // Z partner (wraps k=0 -> 0)

            const float2 Zk = sz[k + (k >> 4)];
            const float2 Zm = sz[km + (km >> 4)];

            const float sxr = Zk.x + Zm.x;            // 2*Fe.re
            const float dyi = Zk.y - Zm.y;            // 2*Fe.im
            const float For = Zk.y + Zm.y;            // 2*Fo.re
            const float Foi = Zm.x - Zk.x;            // 2*Fo.im

            // w' = 0.5 * W_512^k = (bc + i bs) * (CJ2 + i SJ2)
            const float wc = fmaf(bc, CJ2[j], -bs * SJ2[j]);
            const float ws = fmaf(bc, SJ2[j],  bs * CJ2[j]);

            const float P = fmaf(wc, For, -ws * Foi);
            const float Q = fmaf(wc, Foi,  ws * For);

            orow[k] = fmaf(0.5f, sxr, P);             // X[k]
            irow[k] = fmaf(0.5f, dyi, Q);
            orow[256 - k] = fmaf(0.5f, sxr, -P);      // X[256-k] (k=0 -> bin 256)
            irow[256 - k] = fmaf(-0.5f, dyi, Q);
        }
        if (lane == 0) {                // self-paired bin 128: X = Zr - i*Zi
            const float2 Zc = sz[128 + (128 >> 4)];
            orow[128] =  Zc.x;
            irow[128] = -Zc.y;
        }
    }
}

extern "C" void kernel_launch(void* const* d_in, const int* in_sizes, int n_in,
                              void* d_out, int out_size)
{
    const float* x = (const float*)d_in[0];
    float* out = (float*)d_out;
    float* yre = out;                                  // [32768, 257]
    float* yim = out + (long long)NBATCH * NOUT;       // [32768, 257]

    rfft512_warp<<<NBATCH / RPB, 32 * RPB>>>(x, yre, yim);
}